// round 1
// baseline (speedup 1.0000x reference)
#include <cuda_runtime.h>
#include <math.h>

#define NTOK   196
#define CDIM   768
#define BATCH  256
#define NCLS   701

// Scratch: 4 mean vectors per sample, row = (tensor*2 + isFg)*BATCH + b
__device__ float g_V[4 * BATCH * CDIM];

// ---------------------------------------------------------------------------
// Kernel 1: fused SGM per (tensor, sample).
//   Pass 1: read all 196x768 floats -> token energies M[n] (smem) and channel
//           totals T[c] (smem, per-warp staging then reduce).
//   Select: normalize, O(N^2) stable rank, sorted array, gap diff with
//           zero-forcing, argmax (first index on ties) -> k, small-side list.
//   Pass 2: re-read only small-side tokens (<=98, usually ~2; L2-resident),
//           derive fg/bg sums via T - S, write means to g_V.
// ---------------------------------------------------------------------------
__global__ void __launch_bounds__(256)
sgm_kernel(const float* __restrict__ x1, const float* __restrict__ x2) {
    const int b      = blockIdx.x;
    const int tensor = blockIdx.y;
    const float* x = (tensor == 0 ? x1 : x2) + (size_t)b * NTOK * CDIM;

    __shared__ float sT[8][CDIM];     // per-warp channel-sum staging
    __shared__ float sTtot[CDIM];     // final per-channel totals
    __shared__ float sM[NTOK];        // token energies
    __shared__ float sSorted[NTOK];   // sorted normalized energies
    __shared__ float sVal[256];       // generic reduce buffer (also holds Mn)
    __shared__ int   sIdx[256];
    __shared__ int   sList[112];      // small-side token indices
    __shared__ int   sCnt;
    __shared__ float sMnMx[2];

    const int tid  = threadIdx.x;
    const int warp = tid >> 5;
    const int lane = tid & 31;

    // ---------------- Pass 1: M[n] and T[c] ----------------
    float tacc[24];
#pragma unroll
    for (int i = 0; i < 24; i++) tacc[i] = 0.f;

    for (int n = warp; n < NTOK; n += 8) {
        const float4* row = reinterpret_cast<const float4*>(x + (size_t)n * CDIM);
        float msum = 0.f;
#pragma unroll
        for (int i = 0; i < 6; i++) {
            float4 v = row[lane + 32 * i];
            tacc[4*i+0] += v.x; tacc[4*i+1] += v.y;
            tacc[4*i+2] += v.z; tacc[4*i+3] += v.w;
            msum += (v.x + v.y) + (v.z + v.w);
        }
#pragma unroll
        for (int off = 16; off > 0; off >>= 1)
            msum += __shfl_down_sync(0xffffffffu, msum, off);
        if (lane == 0) sM[n] = msum;
    }
    {
        float4* st = reinterpret_cast<float4*>(&sT[warp][0]);
#pragma unroll
        for (int i = 0; i < 6; i++)
            st[lane + 32 * i] = make_float4(tacc[4*i], tacc[4*i+1], tacc[4*i+2], tacc[4*i+3]);
    }
    if (tid == 0) sCnt = 0;
    __syncthreads();

    if (tid < 192) {  // 192 float4 = 768 channels
        float4 t = make_float4(0.f, 0.f, 0.f, 0.f);
#pragma unroll
        for (int w = 0; w < 8; w++) {
            float4 v = reinterpret_cast<float4*>(&sT[w][0])[tid];
            t.x += v.x; t.y += v.y; t.z += v.z; t.w += v.w;
        }
        reinterpret_cast<float4*>(sTtot)[tid] = t;
    }
    __syncthreads();

    // ---------------- min / max of M ----------------
    sVal[tid] = (tid < NTOK) ? sM[tid] : 3.4e38f;
    __syncthreads();
    for (int s = 128; s > 0; s >>= 1) {
        if (tid < s) sVal[tid] = fminf(sVal[tid], sVal[tid + s]);
        __syncthreads();
    }
    if (tid == 0) sMnMx[0] = sVal[0];
    __syncthreads();
    sVal[tid] = (tid < NTOK) ? sM[tid] : -3.4e38f;
    __syncthreads();
    for (int s = 128; s > 0; s >>= 1) {
        if (tid < s) sVal[tid] = fmaxf(sVal[tid], sVal[tid + s]);
        __syncthreads();
    }
    if (tid == 0) sMnMx[1] = sVal[0];
    __syncthreads();

    const float mn  = sMnMx[0];
    const float mx  = sMnMx[1];
    const float inv = 1.f / (mx - mn);

    // ---------------- normalize + stable rank ----------------
    float myMn = 0.f;
    __syncthreads();                       // ensure min/max reduce reads done
    if (tid < NTOK) myMn = (sM[tid] - mn) * inv;
    sVal[tid] = myMn;                      // Mn values live in sVal[0..195]
    __syncthreads();

    int myrank = 0;
    if (tid < NTOK) {
        int r = 0;
        for (int m = 0; m < NTOK; m++) {
            float o = sVal[m];
            r += (o < myMn) || (o == myMn && m < tid);   // stable (argsort) order
        }
        myrank = r;
        sSorted[r] = myMn;
    }
    __syncthreads();

    // ---------------- gap diff + argmax (first index on ties) ----------------
    float dv = -1.f;
    if (tid < NTOK - 1) {
        float s0 = sSorted[tid];
        dv = (s0 == 0.f) ? 0.f : (sSorted[tid + 1] - s0);
    }
    sVal[tid] = dv;
    sIdx[tid] = tid;
    __syncthreads();
    for (int s = 128; s > 0; s >>= 1) {
        if (tid < s) {
            float v2 = sVal[tid + s]; int i2 = sIdx[tid + s];
            if (v2 > sVal[tid] || (v2 == sVal[tid] && i2 < sIdx[tid])) {
                sVal[tid] = v2; sIdx[tid] = i2;
            }
        }
        __syncthreads();
    }
    const int  k         = sIdx[0];
    const bool smallIsFg = (k <= NTOK / 2);

    if (tid < NTOK) {
        bool inSmall = smallIsFg ? (myrank < k) : (myrank >= k);
        if (inSmall) {
            int p = atomicAdd(&sCnt, 1);
            sList[p] = tid;
        }
    }
    __syncthreads();
    const int cnt = sCnt;

    // ---------------- Pass 2: small-side channel sum ----------------
#pragma unroll
    for (int i = 0; i < 24; i++) tacc[i] = 0.f;
    for (int j = warp; j < cnt; j += 8) {
        int n = sList[j];
        const float4* row = reinterpret_cast<const float4*>(x + (size_t)n * CDIM);
#pragma unroll
        for (int i = 0; i < 6; i++) {
            float4 v = row[lane + 32 * i];
            tacc[4*i+0] += v.x; tacc[4*i+1] += v.y;
            tacc[4*i+2] += v.z; tacc[4*i+3] += v.w;
        }
    }
    {
        float4* st = reinterpret_cast<float4*>(&sT[warp][0]);
#pragma unroll
        for (int i = 0; i < 6; i++)
            st[lane + 32 * i] = make_float4(tacc[4*i], tacc[4*i+1], tacc[4*i+2], tacc[4*i+3]);
    }
    __syncthreads();

    if (tid < 192) {
        float4 S = make_float4(0.f, 0.f, 0.f, 0.f);
#pragma unroll
        for (int w = 0; w < 8; w++) {
            float4 v = reinterpret_cast<float4*>(&sT[w][0])[tid];
            S.x += v.x; S.y += v.y; S.z += v.z; S.w += v.w;
        }
        float4 T = reinterpret_cast<float4*>(sTtot)[tid];

        float4 fgs, bgs;
        if (smallIsFg) {
            fgs = S;
            bgs = make_float4(T.x - S.x, T.y - S.y, T.z - S.z, T.w - S.w);
        } else {
            bgs = S;
            fgs = make_float4(T.x - S.x, T.y - S.y, T.z - S.z, T.w - S.w);
        }
        const float fgc = fmaxf((float)k, 1.f);
        const float bgc = fmaxf((float)(NTOK - k), 1.f);
        float4 fg = make_float4(fgs.x / fgc, fgs.y / fgc, fgs.z / fgc, fgs.w / fgc);
        float4 bg = make_float4(bgs.x / bgc, bgs.y / bgc, bgs.z / bgc, bgs.w / bgc);

        float4* vbg = reinterpret_cast<float4*>(&g_V[(size_t)((tensor * 2 + 0) * BATCH + b) * CDIM]);
        float4* vfg = reinterpret_cast<float4*>(&g_V[(size_t)((tensor * 2 + 1) * BATCH + b) * CDIM]);
        vbg[tid] = bg;
        vfg[tid] = fg;
    }
}

// ---------------------------------------------------------------------------
// Kernel 2: out[1024,701] = g_V[1024,768] @ W[768,701] + bias
// SIMT fp32, BM=32 x BN=64 tiles, 256 threads, 4x2 microtile, BK=16.
// ---------------------------------------------------------------------------
#define BM 32
#define BN 64
#define BK 16

__global__ void __launch_bounds__(256)
gemm_kernel(const float* __restrict__ W, const float* __restrict__ bias,
            float* __restrict__ out) {
    __shared__ float As[BK][BM];        // transposed: [k][m]
    __shared__ float Bs[BK][BN];

    const int tid = threadIdx.x;
    const int ty  = tid >> 5;           // 0..7 -> 4 rows each
    const int tx  = tid & 31;           // 0..31 -> 2 cols each
    const int r0  = blockIdx.y * BM;
    const int c0  = blockIdx.x * BN;

    float acc[4][2];
#pragma unroll
    for (int i = 0; i < 4; i++) { acc[i][0] = 0.f; acc[i][1] = 0.f; }

    const int a_row = tid >> 2;         // 0..63 (use tid<128)
    const int a_c4  = tid & 3;

    for (int k0 = 0; k0 < CDIM; k0 += BK) {
        if (tid < 128) {
            float4 va = *reinterpret_cast<const float4*>(
                &g_V[(size_t)(r0 + a_row) * CDIM + k0 + 4 * a_c4]);
            As[4*a_c4+0][a_row] = va.x;
            As[4*a_c4+1][a_row] = va.y;
            As[4*a_c4+2][a_row] = va.z;
            As[4*a_c4+3][a_row] = va.w;
        }
        // B tile: 16x64 = 1024 floats, coalesced, 4 per thread
#pragma unroll
        for (int it = 0; it < 4; it++) {
            int flat = tid + it * 256;
            int kk = flat >> 6;          // /64
            int cc = flat & 63;
            int c  = c0 + cc;
            Bs[kk][cc] = (c < NCLS) ? W[(size_t)(k0 + kk) * NCLS + c] : 0.f;
        }
        __syncthreads();

#pragma unroll
        for (int kk = 0; kk < BK; kk++) {
            float4 a = *reinterpret_cast<float4*>(&As[kk][ty * 4]);
            float b0 = Bs[kk][tx * 2 + 0];
            float b1 = Bs[kk][tx * 2 + 1];
            acc[0][0] += a.x * b0; acc[0][1] += a.x * b1;
            acc[1][0] += a.y * b0; acc[1][1] += a.y * b1;
            acc[2][0] += a.z * b0; acc[2][1] += a.z * b1;
            acc[3][0] += a.w * b0; acc[3][1] += a.w * b1;
        }
        __syncthreads();
    }

#pragma unroll
    for (int j = 0; j < 2; j++) {
        int c = c0 + tx * 2 + j;
        if (c < NCLS) {
            float bb = bias[c];
#pragma unroll
            for (int i = 0; i < 4; i++) {
                out[(size_t)(r0 + ty * 4 + i) * NCLS + c] = acc[i][j] + bb;
            }
        }
    }
}

// ---------------------------------------------------------------------------
extern "C" void kernel_launch(void* const* d_in, const int* in_sizes, int n_in,
                              void* d_out, int out_size) {
    // Defensive input mapping by element count:
    //   x1, x2: 256*196*768 = 38535168 (first two in order)
    //   W: 768*701 = 538368;  b: 701
    const float* x1 = nullptr;
    const float* x2 = nullptr;
    const float* W  = nullptr;
    const float* bb = nullptr;
    for (int i = 0; i < n_in; i++) {
        if (in_sizes[i] == BATCH * NTOK * CDIM) {
            if (!x1) x1 = (const float*)d_in[i];
            else if (!x2) x2 = (const float*)d_in[i];
        } else if (in_sizes[i] == CDIM * NCLS) {
            W = (const float*)d_in[i];
        } else if (in_sizes[i] == NCLS) {
            bb = (const float*)d_in[i];
        }
    }
    float* out = (float*)d_out;

    dim3 g1(BATCH, 2);
    sgm_kernel<<<g1, 256>>>(x1, x2);

    dim3 g2((NCLS + BN - 1) / BN, (4 * BATCH) / BM);
    gemm_kernel<<<g2, 256>>>(W, bb, out);
}